// round 11
// baseline (speedup 1.0000x reference)
#include <cuda_runtime.h>
#include <string.h>

#define DIM   100
#define KBS   4950
#define NN    (DIM * DIM)          // 10000
#define MAXB  2048
#define KC    20                   // K-chunk (5 chunks of 20)

// Sanctioned scratch (__device__ globals; no runtime allocation).
__device__ float2 g_U [NN];        // U[r][c]  row-major
__device__ float2 g_UT[NN];        // U^T: g_UT[l*DIM + j] = U[j][l]
__device__ float2 g_L [MAXB * NN];
__device__ float4 g_rot[KBS];      // {cos th, sin th, cos ph, sin ph}
__device__ float2 g_dph[DIM];      // {cos d, sin d}

// ---------------- packed f32x2 helpers (Blackwell f32x2 pipe) ----------------
__device__ __forceinline__ unsigned long long pk2(float lo, float hi) {
    unsigned long long r;
    asm("mov.b64 %0, {%1, %2};" : "=l"(r) : "f"(lo), "f"(hi));
    return r;
}
__device__ __forceinline__ unsigned long long f2ull(float2 v) {
    unsigned long long r; memcpy(&r, &v, 8); return r;
}
__device__ __forceinline__ float2 ull2f(unsigned long long v) {
    float2 f; memcpy(&f, &v, 8); return f;
}
__device__ __forceinline__ void fma2(unsigned long long& d,
                                     unsigned long long a,
                                     unsigned long long b) {
    asm("fma.rn.f32x2 %0, %1, %2, %0;" : "+l"(d) : "l"(a), "l"(b));
}

// ---------------------------------------------------------------------------
// Kernel 0: precompute rotation coefficients once.
// ---------------------------------------------------------------------------
__global__ void rot_prep(const float* __restrict__ theta,
                         const float* __restrict__ phi,
                         const float* __restrict__ diag) {
    const int i = blockIdx.x * blockDim.x + threadIdx.x;
    if (i < KBS) {
        float st, ct, sp, cp;
        sincosf(theta[i], &st, &ct);
        sincosf(phi[i],   &sp, &cp);
        g_rot[i] = make_float4(ct, st, cp, sp);
    }
    if (i < DIM) {
        float sd, cd;
        sincosf(diag[i], &sd, &cd);
        g_dph[i] = make_float2(cd, sd);
    }
}

// ---------------------------------------------------------------------------
// Kernel 1: build U = D * T_K ... T_1.  One CTA per column; serial layer scan
// with next-layer coefficient prefetch. Writes g_U and g_UT.
// ---------------------------------------------------------------------------
__global__ void build_U() {
    __shared__ float2 col[DIM];
    const int c   = blockIdx.x;
    const int tid = threadIdx.x;          // blockDim = 64

    for (int r = tid; r < DIM; r += 64)
        col[r] = make_float2(r == c ? 1.0f : 0.0f, 0.0f);
    __syncthreads();

    float4 rc_next = make_float4(1.f, 0.f, 1.f, 0.f);
    if (tid < 50) rc_next = g_rot[tid];

    int off = 0;
    for (int layer = 0; layer < DIM; ++layer) {
        const int start = layer & 1;
        const int np    = (DIM - start) >> 1;
        const float4 rc = rc_next;

        const int noff = off + np;
        if (layer + 1 < DIM) {
            const int nstart = (layer + 1) & 1;
            const int nnp    = (DIM - nstart) >> 1;
            if (tid < nnp) rc_next = g_rot[noff + tid];
        }

        if (tid < np) {
            const int m = start + 2 * tid;
            const float2 rm = col[m];
            const float2 rn = col[m + 1];
            const float er = rc.z * rm.x - rc.w * rm.y;   // e^{i ph} * rm
            const float ei = rc.z * rm.y + rc.w * rm.x;
            col[m]     = make_float2(rc.x * er - rc.y * rn.x,
                                     rc.x * ei - rc.y * rn.y);
            col[m + 1] = make_float2(rc.y * er + rc.x * rn.x,
                                     rc.y * ei + rc.x * rn.y);
        }
        off = noff;
        __syncthreads();
    }

    for (int r = tid; r < DIM; r += 64) {
        const float2 d = g_dph[r];
        const float2 v = col[r];
        const float2 u = make_float2(d.x * v.x - d.y * v.y,
                                     d.x * v.y + d.y * v.x);
        g_U [r * DIM + c] = u;
        g_UT[c * DIM + r] = u;
    }
}

// ---------------------------------------------------------------------------
// Kernel 2: GEMM1  L_b = U @ X_b for TWO batches per CTA.
// U tile (As) is batch-invariant: its LDS loads + pk2 packing are shared
// across both batches' 80 FMA2 per kk.  smem = 16000 + 2*16000 = 48000 B.
// ---------------------------------------------------------------------------
__global__ void __launch_bounds__(512)
gemm1_UX(const float* __restrict__ xre, const float* __restrict__ xim,
         int nbatch) {
    __shared__ float2 As[DIM * KC];       // U   [row][kk]   (broadcast reads)
    __shared__ float2 Bs[2][KC * DIM];    // X   [kk][col]   per batch

    const int tid   = threadIdx.x;
    const int b0    = 2 * blockIdx.x;
    const int b1    = b0 + 1;
    const bool has1 = (b1 < nbatch);
    const int base0 = b0 * NN;
    const int base1 = b1 * NN;

    const bool active = tid < 500;
    const int ti = tid / 25;
    const int tj = tid - ti * 25;
    const int i0 = ti * 5;

    unsigned long long acc0[5][4], acc1[5][4];
    #pragma unroll
    for (int r = 0; r < 5; ++r)
        #pragma unroll
        for (int c = 0; c < 4; ++c) { acc0[r][c] = 0ull; acc1[r][c] = 0ull; }

    for (int kc = 0; kc < DIM; kc += KC) {
        for (int e = tid; e < DIM * KC; e += 512) {
            const int row = e / KC;
            const int kk  = e - row * KC;
            As[e] = g_U[row * DIM + kc + kk];
        }
        for (int e = tid; e < KC * DIM; e += 512) {
            const int kk  = e / DIM;
            const int col = e - kk * DIM;
            const int off = (kc + kk) * DIM + col;
            Bs[0][e] = make_float2(xre[base0 + off], xim[base0 + off]);
            if (has1)
                Bs[1][e] = make_float2(xre[base1 + off], xim[base1 + off]);
        }
        __syncthreads();

        if (active) {
            #pragma unroll 5
            for (int kk = 0; kk < KC; ++kk) {
                unsigned long long axx[5], ayn[5];
                #pragma unroll
                for (int r = 0; r < 5; ++r) {
                    const float2 av = As[(i0 + r) * KC + kk];   // broadcast
                    axx[r] = pk2(av.x, av.x);
                    ayn[r] = pk2(-av.y, av.y);
                }
                #pragma unroll
                for (int c = 0; c < 4; ++c) {
                    const int bi = kk * DIM + 25 * c + tj;      // conflict-free
                    {
                        const float2 bv = Bs[0][bi];
                        const unsigned long long bxy = f2ull(bv);
                        const unsigned long long byx = pk2(bv.y, bv.x);
                        #pragma unroll
                        for (int r = 0; r < 5; ++r) {
                            fma2(acc0[r][c], axx[r], bxy);
                            fma2(acc0[r][c], ayn[r], byx);
                        }
                    }
                    {
                        const float2 bv = Bs[1][bi];
                        const unsigned long long bxy = f2ull(bv);
                        const unsigned long long byx = pk2(bv.y, bv.x);
                        #pragma unroll
                        for (int r = 0; r < 5; ++r) {
                            fma2(acc1[r][c], axx[r], bxy);
                            fma2(acc1[r][c], ayn[r], byx);
                        }
                    }
                }
            }
        }
        __syncthreads();
    }

    if (active) {
        #pragma unroll
        for (int r = 0; r < 5; ++r)
            #pragma unroll
            for (int c = 0; c < 4; ++c) {
                const int off = (i0 + r) * DIM + 25 * c + tj;
                g_L[base0 + off] = ull2f(acc0[r][c]);
                if (has1) g_L[base1 + off] = ull2f(acc1[r][c]);
            }
    }
}

// ---------------------------------------------------------------------------
// Kernel 3: GEMM2  Re(O_b) = Lr@Ur^T + Li@Ui^T for TWO batches per CTA.
// U^T tile (UsT) is batch-invariant -> its conflict-free loads shared across
// both batches.  smem = 2*16000 + 16000 = 48000 B.
// ---------------------------------------------------------------------------
__global__ void __launch_bounds__(512)
gemm2_LUh(float* __restrict__ outf, int out_floats, int nbatch) {
    __shared__ float2 As[2][DIM * KC];    // L   [i][kk]  per batch (broadcast)
    __shared__ float2 UsT[KC * DIM];      // U^T [kk][j]  shared

    const int tid   = threadIdx.x;
    const int b0    = 2 * blockIdx.x;
    const int b1    = b0 + 1;
    const bool has1 = (b1 < nbatch);
    const int base0 = b0 * NN;
    const int base1 = b1 * NN;

    const bool active = tid < 500;
    const int ti = tid / 25;
    const int tj = tid - ti * 25;
    const int i0 = ti * 5;

    unsigned long long acc0[5][4], acc1[5][4];
    #pragma unroll
    for (int r = 0; r < 5; ++r)
        #pragma unroll
        for (int c = 0; c < 4; ++c) { acc0[r][c] = 0ull; acc1[r][c] = 0ull; }

    for (int kc = 0; kc < DIM; kc += KC) {
        for (int e = tid; e < DIM * KC; e += 512) {
            const int row = e / KC;
            const int kk  = e - row * KC;
            const int off = row * DIM + kc + kk;
            As[0][e] = g_L[base0 + off];
            if (has1) As[1][e] = g_L[base1 + off];
        }
        for (int e = tid; e < KC * DIM; e += 512) {
            const int kk = e / DIM;
            const int j  = e - kk * DIM;
            UsT[e] = g_UT[(kc + kk) * DIM + j];   // coalesced
        }
        __syncthreads();

        if (active) {
            #pragma unroll 5
            for (int kk = 0; kk < KC; ++kk) {
                unsigned long long uc[4];
                #pragma unroll
                for (int c = 0; c < 4; ++c)
                    uc[c] = f2ull(UsT[kk * DIM + 25 * c + tj]); // conflict-free
                #pragma unroll
                for (int r = 0; r < 5; ++r) {
                    const unsigned long long ar0 =
                        f2ull(As[0][(i0 + r) * KC + kk]);       // broadcast
                    const unsigned long long ar1 =
                        f2ull(As[1][(i0 + r) * KC + kk]);
                    #pragma unroll
                    for (int c = 0; c < 4; ++c) {
                        fma2(acc0[r][c], ar0, uc[c]);
                        fma2(acc1[r][c], ar1, uc[c]);
                    }
                }
            }
        }
        __syncthreads();
    }

    if (active) {
        #pragma unroll
        for (int r = 0; r < 5; ++r)
            #pragma unroll
            for (int c = 0; c < 4; ++c) {
                const int off = (i0 + r) * DIM + 25 * c + tj;
                const float2 s0 = ull2f(acc0[r][c]);
                if (base0 + off < out_floats)
                    outf[base0 + off] = s0.x + s0.y;
                if (has1) {
                    const float2 s1 = ull2f(acc1[r][c]);
                    if (base1 + off < out_floats)
                        outf[base1 + off] = s1.x + s1.y;
                }
            }
    }
}

// Diagnostic fallback: binding anomaly -> numeric mismatch, never a crash.
__global__ void diag_mark_kernel(float* out) { out[0] = 0.0f; }

extern "C" void kernel_launch(void* const* d_in, const int* in_sizes, int n_in,
                              void* d_out, int out_size) {
    // Unit detection (elements vs bytes) via the 100-element diag array.
    int smin = 0x7fffffff;
    for (int i = 0; i < n_in; ++i)
        if (in_sizes[i] < smin) smin = in_sizes[i];

    int unit = 0;
    if (smin == DIM)          unit = 1;
    else if (smin == DIM * 4) unit = 4;

    const float* xre = nullptr; const float* xim = nullptr;
    const float* theta = nullptr; const float* phi = nullptr;
    const float* diag = nullptr;
    int nbatch = 0, big = 0;
    bool ok = (unit != 0) && (n_in == 5);

    if (ok) {
        int norm[8];
        int diag_slot = -1;
        for (int i = 0; i < n_in; ++i) {
            norm[i] = in_sizes[i] / unit;
            if (norm[i] == DIM) diag_slot = i;
            if (norm[i] > big) big = norm[i];
        }
        if (diag_slot == 0 && norm[1] == KBS && norm[2] == KBS) {
            // alphabetical metadata order: diag, phi, theta, x_re, x_im
            diag  = (const float*)d_in[0];
            phi   = (const float*)d_in[1];
            theta = (const float*)d_in[2];
            xre   = (const float*)d_in[3];
            xim   = (const float*)d_in[4];
        } else {
            for (int i = 0; i < n_in; ++i) {
                const float* p = (const float*)d_in[i];
                if (norm[i] == KBS)      { if (!theta) theta = p; else phi = p; }
                else if (norm[i] == DIM) { diag = p; }
                else if (norm[i] == big) { if (!xre) xre = p; else xim = p; }
            }
        }
        nbatch = big / NN;
        ok = xre && xim && theta && phi && diag &&
             nbatch > 0 && nbatch <= MAXB && (big == nbatch * NN);
    }

    if (!ok) {
        diag_mark_kernel<<<1, 1>>>((float*)d_out);
        return;
    }

    // Confirmed output contract: float32 real parts, out_size = B*N*N floats.
    const int want = nbatch * NN;
    const int out_floats = (out_size < want) ? out_size : want;
    const int npair = (nbatch + 1) / 2;

    rot_prep<<<(KBS + 127) / 128, 128>>>(theta, phi, diag);
    build_U<<<DIM, 64>>>();
    gemm1_UX<<<npair, 512>>>(xre, xim, nbatch);
    gemm2_LUh<<<npair, 512>>>((float*)d_out, out_floats, nbatch);
}

// round 12
// speedup vs baseline: 1.1529x; 1.1529x over previous
#include <cuda_runtime.h>
#include <string.h>

#define DIM   100
#define KBS   4950
#define NN    (DIM * DIM)          // 10000
#define MAXB  2048
#define KC1   10                   // K-chunk (10 chunks), both GEMMs
#define NCH   (DIM / KC1)          // 10
#define CHA   (DIM * KC1)          // 1000 elements per A-chunk
#define CHB   (KC1 * DIM)          // 1000 elements per B-chunk

// Sanctioned scratch (__device__ globals; no runtime allocation).
__device__ float2 g_U [NN];        // U[r][c]  row-major
__device__ float2 g_UT[NN];        // U^T: g_UT[l*DIM + j] = U[j][l]
__device__ float2 g_L [MAXB * NN];
__device__ float4 g_rot[KBS];      // {cos th, sin th, cos ph, sin ph}
__device__ float2 g_dph[DIM];      // {cos d, sin d}

// ---------------- packed f32x2 helpers (Blackwell f32x2 pipe) ----------------
__device__ __forceinline__ unsigned long long pk2(float lo, float hi) {
    unsigned long long r;
    asm("mov.b64 %0, {%1, %2};" : "=l"(r) : "f"(lo), "f"(hi));
    return r;
}
__device__ __forceinline__ unsigned long long f2ull(float2 v) {
    unsigned long long r; memcpy(&r, &v, 8); return r;
}
__device__ __forceinline__ float2 ull2f(unsigned long long v) {
    float2 f; memcpy(&f, &v, 8); return f;
}
__device__ __forceinline__ void fma2(unsigned long long& d,
                                     unsigned long long a,
                                     unsigned long long b) {
    asm("fma.rn.f32x2 %0, %1, %2, %0;" : "+l"(d) : "l"(a), "l"(b));
}

// ---------------------------------------------------------------------------
// Kernel 0: precompute rotation coefficients once.
// ---------------------------------------------------------------------------
__global__ void rot_prep(const float* __restrict__ theta,
                         const float* __restrict__ phi,
                         const float* __restrict__ diag) {
    const int i = blockIdx.x * blockDim.x + threadIdx.x;
    if (i < KBS) {
        float st, ct, sp, cp;
        sincosf(theta[i], &st, &ct);
        sincosf(phi[i],   &sp, &cp);
        g_rot[i] = make_float4(ct, st, cp, sp);
    }
    if (i < DIM) {
        float sd, cd;
        sincosf(diag[i], &sd, &cd);
        g_dph[i] = make_float2(cd, sd);
    }
}

// ---------------------------------------------------------------------------
// Kernel 1: build U = D * T_K ... T_1.  One CTA per column; serial layer scan
// with next-layer coefficient prefetch. Writes g_U and g_UT.
// ---------------------------------------------------------------------------
__global__ void build_U() {
    __shared__ float2 col[DIM];
    const int c   = blockIdx.x;
    const int tid = threadIdx.x;          // blockDim = 64

    for (int r = tid; r < DIM; r += 64)
        col[r] = make_float2(r == c ? 1.0f : 0.0f, 0.0f);
    __syncthreads();

    float4 rc_next = make_float4(1.f, 0.f, 1.f, 0.f);
    if (tid < 50) rc_next = g_rot[tid];

    int off = 0;
    for (int layer = 0; layer < DIM; ++layer) {
        const int start = layer & 1;
        const int np    = (DIM - start) >> 1;
        const float4 rc = rc_next;

        const int noff = off + np;
        if (layer + 1 < DIM) {
            const int nstart = (layer + 1) & 1;
            const int nnp    = (DIM - nstart) >> 1;
            if (tid < nnp) rc_next = g_rot[noff + tid];
        }

        if (tid < np) {
            const int m = start + 2 * tid;
            const float2 rm = col[m];
            const float2 rn = col[m + 1];
            const float er = rc.z * rm.x - rc.w * rm.y;   // e^{i ph} * rm
            const float ei = rc.z * rm.y + rc.w * rm.x;
            col[m]     = make_float2(rc.x * er - rc.y * rn.x,
                                     rc.x * ei - rc.y * rn.y);
            col[m + 1] = make_float2(rc.y * er + rc.x * rn.x,
                                     rc.y * ei + rc.x * rn.y);
        }
        off = noff;
        __syncthreads();
    }

    for (int r = tid; r < DIM; r += 64) {
        const float2 d = g_dph[r];
        const float2 v = col[r];
        const float2 u = make_float2(d.x * v.x - d.y * v.y,
                                     d.x * v.y + d.y * v.x);
        g_U [r * DIM + c] = u;
        g_UT[c * DIM + r] = u;
    }
}

// ---------------------------------------------------------------------------
// Kernel 2: GEMM1  L_b = U @ X_b.  SINGLE batch per CTA (FMA-issue bound ->
// operand sharing can't help; round-10 pairing regressed it).
// Double-buffered K-chunks: LDG for chunk c+1 issued before compute of chunk
// c, STS after -> gmem latency hidden behind 40 FMA2/kk. smem 32 KB.
// ---------------------------------------------------------------------------
__global__ void __launch_bounds__(512)
gemm1_UX(const float* __restrict__ xre, const float* __restrict__ xim) {
    __shared__ float2 As[2][CHA];   // U  [row][kk]
    __shared__ float2 Bs[2][CHB];   // X  [kk][col]

    const int tid  = threadIdx.x;
    const int base = blockIdx.x * NN;

    const bool active = tid < 500;
    const int ti = tid / 25;
    const int tj = tid - ti * 25;
    const int i0 = ti * 5;

    // staging registers (each thread owns elements tid and tid+512 of each chunk)
    const int  ea1 = tid + 512;
    const bool ha1 = ea1 < CHA;          // == (tid < 488)
    float2 sa0, sa1, sb0, sb1;

    // ---- load chunk 0 ----
    {
        const int r0 = tid / KC1, k0 = tid - r0 * KC1;
        sa0 = g_U[r0 * DIM + k0];
        if (ha1) { const int r1 = ea1 / KC1, k1 = ea1 - r1 * KC1;
                   sa1 = g_U[r1 * DIM + k1]; }
        const int kb0 = tid / DIM, cb0 = tid - kb0 * DIM;
        const int gg0 = base + kb0 * DIM + cb0;
        sb0 = make_float2(xre[gg0], xim[gg0]);
        if (ha1) { const int kb1 = ea1 / DIM, cb1 = ea1 - kb1 * DIM;
                   const int gg1 = base + kb1 * DIM + cb1;
                   sb1 = make_float2(xre[gg1], xim[gg1]); }
    }
    As[0][tid] = sa0; if (ha1) As[0][ea1] = sa1;
    Bs[0][tid] = sb0; if (ha1) Bs[0][ea1] = sb1;
    __syncthreads();

    unsigned long long acc[5][4];
    #pragma unroll
    for (int r = 0; r < 5; ++r)
        #pragma unroll
        for (int c = 0; c < 4; ++c) acc[r][c] = 0ull;

    for (int ch = 0; ch < NCH; ++ch) {
        const int cur = ch & 1;

        // issue next chunk's LDGs (no use until after compute)
        if (ch + 1 < NCH) {
            const int kofs = (ch + 1) * KC1;
            const int r0 = tid / KC1, k0 = tid - r0 * KC1;
            sa0 = g_U[r0 * DIM + kofs + k0];
            if (ha1) { const int r1 = ea1 / KC1, k1 = ea1 - r1 * KC1;
                       sa1 = g_U[r1 * DIM + kofs + k1]; }
            const int kb0 = tid / DIM, cb0 = tid - kb0 * DIM;
            const int gg0 = base + (kofs + kb0) * DIM + cb0;
            sb0 = make_float2(xre[gg0], xim[gg0]);
            if (ha1) { const int kb1 = ea1 / DIM, cb1 = ea1 - kb1 * DIM;
                       const int gg1 = base + (kofs + kb1) * DIM + cb1;
                       sb1 = make_float2(xre[gg1], xim[gg1]); }
        }

        if (active) {
            #pragma unroll
            for (int kk = 0; kk < KC1; ++kk) {
                unsigned long long axx[5], ayn[5];
                #pragma unroll
                for (int r = 0; r < 5; ++r) {
                    const float2 av = As[cur][(i0 + r) * KC1 + kk]; // broadcast
                    axx[r] = pk2(av.x, av.x);
                    ayn[r] = pk2(-av.y, av.y);
                }
                #pragma unroll
                for (int c = 0; c < 4; ++c) {
                    const float2 bv = Bs[cur][kk * DIM + 25 * c + tj]; // cf-free
                    const unsigned long long bxy = f2ull(bv);
                    const unsigned long long byx = pk2(bv.y, bv.x);
                    #pragma unroll
                    for (int r = 0; r < 5; ++r) {
                        fma2(acc[r][c], axx[r], bxy);
                        fma2(acc[r][c], ayn[r], byx);
                    }
                }
            }
        }

        if (ch + 1 < NCH) {
            const int nxt = cur ^ 1;
            As[nxt][tid] = sa0; if (ha1) As[nxt][ea1] = sa1;
            Bs[nxt][tid] = sb0; if (ha1) Bs[nxt][ea1] = sb1;
        }
        __syncthreads();
    }

    if (active) {
        #pragma unroll
        for (int r = 0; r < 5; ++r)
            #pragma unroll
            for (int c = 0; c < 4; ++c)
                g_L[base + (i0 + r) * DIM + 25 * c + tj] = ull2f(acc[r][c]);
    }
}

// ---------------------------------------------------------------------------
// Kernel 3: GEMM2  Re(O_b) = Lr@Ur^T + Li@Ui^T for TWO batches per CTA
// (U^T operand batch-invariant: proven win in round 10). Double-buffered
// K-chunks as in gemm1. smem = 2*(2*8000 + 8000) = 48000 B (static limit).
// ---------------------------------------------------------------------------
__global__ void __launch_bounds__(512)
gemm2_LUh(float* __restrict__ outf, int out_floats, int nbatch) {
    __shared__ float2 As[2][2][CHA];   // [buf][batch][i*KC1+kk]
    __shared__ float2 UsT[2][CHB];     // [buf][kk*DIM+j]

    const int tid   = threadIdx.x;
    const int b0    = 2 * blockIdx.x;
    const bool has1 = (b0 + 1 < nbatch);
    const int base0 = b0 * NN;
    const int base1 = base0 + (has1 ? NN : 0);   // safe alias if no batch 1

    const bool active = tid < 500;
    const int ti = tid / 25;
    const int tj = tid - ti * 25;
    const int i0 = ti * 5;

    const int  ea1 = tid + 512;
    const bool ha1 = ea1 < CHA;
    float2 sl00, sl01, sl10, sl11, su0, su1;

    // ---- load chunk 0 ----
    {
        const int r0 = tid / KC1, k0 = tid - r0 * KC1;
        const int o0 = r0 * DIM + k0;
        sl00 = g_L[base0 + o0];
        sl10 = g_L[base1 + o0];
        if (ha1) { const int r1 = ea1 / KC1, k1 = ea1 - r1 * KC1;
                   const int o1 = r1 * DIM + k1;
                   sl01 = g_L[base0 + o1];
                   sl11 = g_L[base1 + o1]; }
        su0 = g_UT[tid];                       // (0*KC1+kk)*DIM+j == e
        if (ha1) su1 = g_UT[ea1];
    }
    As[0][0][tid] = sl00; As[0][1][tid] = sl10;
    UsT[0][tid]   = su0;
    if (ha1) { As[0][0][ea1] = sl01; As[0][1][ea1] = sl11; UsT[0][ea1] = su1; }
    __syncthreads();

    unsigned long long acc0[5][4], acc1[5][4];
    #pragma unroll
    for (int r = 0; r < 5; ++r)
        #pragma unroll
        for (int c = 0; c < 4; ++c) { acc0[r][c] = 0ull; acc1[r][c] = 0ull; }

    for (int ch = 0; ch < NCH; ++ch) {
        const int cur = ch & 1;

        if (ch + 1 < NCH) {
            const int kofs = (ch + 1) * KC1;
            const int r0 = tid / KC1, k0 = tid - r0 * KC1;
            const int o0 = r0 * DIM + kofs + k0;
            sl00 = g_L[base0 + o0];
            sl10 = g_L[base1 + o0];
            if (ha1) { const int r1 = ea1 / KC1, k1 = ea1 - r1 * KC1;
                       const int o1 = r1 * DIM + kofs + k1;
                       sl01 = g_L[base0 + o1];
                       sl11 = g_L[base1 + o1]; }
            const int ku0 = tid / DIM, ju0 = tid - ku0 * DIM;
            su0 = g_UT[(kofs + ku0) * DIM + ju0];
            if (ha1) { const int ku1 = ea1 / DIM, ju1 = ea1 - ku1 * DIM;
                       su1 = g_UT[(kofs + ku1) * DIM + ju1]; }
        }

        if (active) {
            #pragma unroll
            for (int kk = 0; kk < KC1; ++kk) {
                unsigned long long uc[4];
                #pragma unroll
                for (int c = 0; c < 4; ++c)
                    uc[c] = f2ull(UsT[cur][kk * DIM + 25 * c + tj]); // cf-free
                #pragma unroll
                for (int r = 0; r < 5; ++r) {
                    const unsigned long long ar0 =
                        f2ull(As[cur][0][(i0 + r) * KC1 + kk]);      // broadcast
                    const unsigned long long ar1 =
                        f2ull(As[cur][1][(i0 + r) * KC1 + kk]);
                    #pragma unroll
                    for (int c = 0; c < 4; ++c) {
                        fma2(acc0[r][c], ar0, uc[c]);
                        fma2(acc1[r][c], ar1, uc[c]);
                    }
                }
            }
        }

        if (ch + 1 < NCH) {
            const int nxt = cur ^ 1;
            As[nxt][0][tid] = sl00; As[nxt][1][tid] = sl10;
            UsT[nxt][tid]   = su0;
            if (ha1) { As[nxt][0][ea1] = sl01; As[nxt][1][ea1] = sl11;
                       UsT[nxt][ea1] = su1; }
        }
        __syncthreads();
    }

    if (active) {
        #pragma unroll
        for (int r = 0; r < 5; ++r)
            #pragma unroll
            for (int c = 0; c < 4; ++c) {
                const int off = (i0 + r) * DIM + 25 * c + tj;
                const float2 s0 = ull2f(acc0[r][c]);
                if (base0 + off < out_floats)
                    outf[base0 + off] = s0.x + s0.y;
                if (has1) {
                    const float2 s1 = ull2f(acc1[r][c]);
                    if (base1 + off < out_floats)
                        outf[base1 + off] = s1.x + s1.y;
                }
            }
    }
}

// Diagnostic fallback: binding anomaly -> numeric mismatch, never a crash.
__global__ void diag_mark_kernel(float* out) { out[0] = 0.0f; }

extern "C" void kernel_launch(void* const* d_in, const int* in_sizes, int n_in,
                              void* d_out, int out_size) {
    // Unit detection (elements vs bytes) via the 100-element diag array.
    int smin = 0x7fffffff;
    for (int i = 0; i < n_in; ++i)
        if (in_sizes[i] < smin) smin = in_sizes[i];

    int unit = 0;
    if (smin == DIM)          unit = 1;
    else if (smin == DIM * 4) unit = 4;

    const float* xre = nullptr; const float* xim = nullptr;
    const float* theta = nullptr; const float* phi = nullptr;
    const float* diag = nullptr;
    int nbatch = 0, big = 0;
    bool ok = (unit != 0) && (n_in == 5);

    if (ok) {
        int norm[8];
        int diag_slot = -1;
        for (int i = 0; i < n_in; ++i) {
            norm[i] = in_sizes[i] / unit;
            if (norm[i] == DIM) diag_slot = i;
            if (norm[i] > big) big = norm[i];
        }
        if (diag_slot == 0 && norm[1] == KBS && norm[2] == KBS) {
            // alphabetical metadata order: diag, phi, theta, x_re, x_im
            diag  = (const float*)d_in[0];
            phi   = (const float*)d_in[1];
            theta = (const float*)d_in[2];
            xre   = (const float*)d_in[3];
            xim   = (const float*)d_in[4];
        } else {
            for (int i = 0; i < n_in; ++i) {
                const float* p = (const float*)d_in[i];
                if (norm[i] == KBS)      { if (!theta) theta = p; else phi = p; }
                else if (norm[i] == DIM) { diag = p; }
                else if (norm[i] == big) { if (!xre) xre = p; else xim = p; }
            }
        }
        nbatch = big / NN;
        ok = xre && xim && theta && phi && diag &&
             nbatch > 0 && nbatch <= MAXB && (big == nbatch * NN);
    }

    if (!ok) {
        diag_mark_kernel<<<1, 1>>>((float*)d_out);
        return;
    }

    // Confirmed output contract: float32 real parts, out_size = B*N*N floats.
    const int want = nbatch * NN;
    const int out_floats = (out_size < want) ? out_size : want;
    const int npair = (nbatch + 1) / 2;

    rot_prep<<<(KBS + 127) / 128, 128>>>(theta, phi, diag);
    build_U<<<DIM, 64>>>();
    gemm1_UX<<<nbatch, 512>>>(xre, xim);
    gemm2_LUh<<<npair, 512>>>((float*)d_out, out_floats, nbatch);
}

// round 14
// speedup vs baseline: 1.7541x; 1.5216x over previous
#include <cuda_runtime.h>
#include <cuda_bf16.h>
#include <string.h>
#include <stdint.h>

#define DIM   100
#define KBS   4950
#define NN    (DIM * DIM)
#define MAXB  2048

#define NT 13      // n8 tiles  (104 = pad of 100)
#define KT 7       // k16 tiles (112 = pad of 100)

// ---- device scratch (no runtime allocation) ----
__device__ float2  g_U[NN];
__device__ float4  g_rot[KBS];
__device__ float2  g_dph[DIM];
// A1 frags: [mat(2)][split(2)][mtile(8)][ktile(7)][lane(32)][reg(4)]
__device__ uint32_t g_A1[2 * 2 * 8 * KT * 32 * 4];
// B2 frags: [mat(2)][split(2)][ktile(7)][ntile(13)][lane(32)][reg(2)]
__device__ uint32_t g_B2[2 * 2 * KT * NT * 32 * 2];

// ---------------- helpers ----------------
__device__ __forceinline__ void hl_split(float v0, float v1,
                                         uint32_t& h, uint32_t& l) {
    const __nv_bfloat16 h0 = __float2bfloat16(v0);
    const __nv_bfloat16 h1 = __float2bfloat16(v1);
    h = (uint32_t)__bfloat16_as_ushort(h0)
      | ((uint32_t)__bfloat16_as_ushort(h1) << 16);
    const __nv_bfloat16 l0 = __float2bfloat16(v0 - __bfloat162float(h0));
    const __nv_bfloat16 l1 = __float2bfloat16(v1 - __bfloat162float(h1));
    l = (uint32_t)__bfloat16_as_ushort(l0)
      | ((uint32_t)__bfloat16_as_ushort(l1) << 16);
}
__device__ __forceinline__ void mma16816(float* d, const uint32_t* a,
                                         uint32_t b0, uint32_t b1) {
    asm volatile(
        "mma.sync.aligned.m16n8k16.row.col.f32.bf16.bf16.f32 "
        "{%0,%1,%2,%3}, {%4,%5,%6,%7}, {%8,%9}, {%0,%1,%2,%3};"
        : "+f"(d[0]), "+f"(d[1]), "+f"(d[2]), "+f"(d[3])
        : "r"(a[0]), "r"(a[1]), "r"(a[2]), "r"(a[3]), "r"(b0), "r"(b1));
}

// ---------------------------------------------------------------------------
// Kernel 0: rotation coefficients.
// ---------------------------------------------------------------------------
__global__ void rot_prep(const float* __restrict__ theta,
                         const float* __restrict__ phi,
                         const float* __restrict__ diag) {
    const int i = blockIdx.x * blockDim.x + threadIdx.x;
    if (i < KBS) {
        float st, ct, sp, cp;
        sincosf(theta[i], &st, &ct);
        sincosf(phi[i],   &sp, &cp);
        g_rot[i] = make_float4(ct, st, cp, sp);
    }
    if (i < DIM) {
        float sd, cd;
        sincosf(diag[i], &sd, &cd);
        g_dph[i] = make_float2(cd, sd);
    }
}

// ---------------------------------------------------------------------------
// Kernel 1: build U (one CTA per column, prefetched serial scan).
// ---------------------------------------------------------------------------
__global__ void build_U() {
    __shared__ float2 col[DIM];
    const int c   = blockIdx.x;
    const int tid = threadIdx.x;          // 64 threads

    for (int r = tid; r < DIM; r += 64)
        col[r] = make_float2(r == c ? 1.0f : 0.0f, 0.0f);
    __syncthreads();

    float4 rc_next = make_float4(1.f, 0.f, 1.f, 0.f);
    if (tid < 50) rc_next = g_rot[tid];

    int off = 0;
    for (int layer = 0; layer < DIM; ++layer) {
        const int start = layer & 1;
        const int np    = (DIM - start) >> 1;
        const float4 rc = rc_next;
        const int noff  = off + np;
        if (layer + 1 < DIM) {
            const int nnp = (DIM - ((layer + 1) & 1)) >> 1;
            if (tid < nnp) rc_next = g_rot[noff + tid];
        }
        if (tid < np) {
            const int m = start + 2 * tid;
            const float2 rm = col[m];
            const float2 rn = col[m + 1];
            const float er = rc.z * rm.x - rc.w * rm.y;
            const float ei = rc.z * rm.y + rc.w * rm.x;
            col[m]     = make_float2(rc.x * er - rc.y * rn.x,
                                     rc.x * ei - rc.y * rn.y);
            col[m + 1] = make_float2(rc.y * er + rc.x * rn.x,
                                     rc.y * ei + rc.x * rn.y);
        }
        off = noff;
        __syncthreads();
    }
    for (int r = tid; r < DIM; r += 64) {
        const float2 d = g_dph[r];
        const float2 v = col[r];
        g_U[r * DIM + c] = make_float2(d.x * v.x - d.y * v.y,
                                       d.x * v.y + d.y * v.x);
    }
}

// U element (mat 0 = Ur, 1 = Ui), zero-padded outside 100x100
__device__ __forceinline__ float u_el(int mat, int r, int k) {
    if (r >= DIM || k >= DIM) return 0.0f;
    const float2 u = g_U[r * DIM + k];
    return mat == 0 ? u.x : u.y;
}

// ---------------------------------------------------------------------------
// Kernel 2: precompute batch-invariant mma fragments of Ur/Ui.
// ---------------------------------------------------------------------------
__global__ void frag_prep() {
    const int i0 = blockIdx.x * blockDim.x + threadIdx.x;
    const int stride = gridDim.x * blockDim.x;

    const int NA = 2 * 2 * 8 * KT * 32 * 4;
    for (int e = i0; e < NA; e += stride) {
        int t = e;
        const int reg = t & 3;  t >>= 2;
        const int lane = t & 31; t >>= 5;
        const int kt = t % KT;   t /= KT;
        const int mt = t & 7;    t >>= 3;
        const int split = t & 1; t >>= 1;
        const int mat = t;
        const int row = mt * 16 + (lane >> 2) + 8 * (reg & 1);
        const int col = kt * 16 + (lane & 3) * 2 + 8 * (reg >> 1);
        const float v0 = u_el(mat, row, col);
        const float v1 = u_el(mat, row, col + 1);
        uint32_t h, l;
        hl_split(v0, v1, h, l);
        g_A1[e] = split == 0 ? h : l;
    }

    const int NB = 2 * 2 * KT * NT * 32 * 2;
    for (int e = i0; e < NB; e += stride) {
        int t = e;
        const int reg = t & 1;   t >>= 1;
        const int lane = t & 31; t >>= 5;
        const int nt = t % NT;   t /= NT;
        const int kt = t % KT;   t /= KT;
        const int split = t & 1; t >>= 1;
        const int mat = t;
        const int k = kt * 16 + (lane & 3) * 2 + 8 * reg;
        const int n = nt * 8 + (lane >> 2);
        // B[k][n] = U^T[k][n] = U[n][k]
        const float v0 = u_el(mat, n, k);
        const float v1 = u_el(mat, n, k + 1);
        uint32_t h, l;
        hl_split(v0, v1, h, l);
        g_B2[e] = split == 0 ? h : l;
    }
}

// ---------------------------------------------------------------------------
// Kernel 3: fused per-batch HMMA transform.
//   stage 1: P = Ur Xr - Ui Xi ; Q = Ur Xi + Ui Xr   (bf16-split mma)
//   stage 2: Re(O) = P Ur^T + Q Ui^T
// 256 threads = 8 warps; warp w owns output rows 16w..16w+15.
// ---------------------------------------------------------------------------
__global__ void __launch_bounds__(256)
fused_mma(const float* __restrict__ xre, const float* __restrict__ xim,
          float* __restrict__ outf, int out_floats) {
    // transposed, pre-split X chunk: [q(104)][j(8 pair-words)], stride 12
    // (stride 12 makes the 8-lane x 4-word frag read conflict-free)
    __shared__ uint32_t XrH[104 * 12], XrL[104 * 12];
    __shared__ uint32_t XiH[104 * 12], XiL[104 * 12];

    const int tid  = threadIdx.x;
    const int warp = tid >> 5;
    const int lane = tid & 31;
    const int nl   = lane >> 2;       // 0..7
    const int mm   = lane & 3;        // 0..3
    const int base = blockIdx.x * NN;

    float P[NT][4], Q[NT][4];
    #pragma unroll
    for (int n = 0; n < NT; ++n)
        #pragma unroll
        for (int r = 0; r < 4; ++r) { P[n][r] = 0.f; Q[n][r] = 0.f; }

    // -------- stage 1: k-chunk loop --------
    for (int c = 0; c < KT; ++c) {
        __syncthreads();   // previous chunk fully consumed
        // stage chunk: pair j covers rows p = 16c+2j, 16c+2j+1
        for (int e = tid; e < 8 * 104; e += 256) {
            const int j = e / 104;          // 0..7
            const int q = e - j * 104;      // 0..103
            const int p = 16 * c + 2 * j;
            float r0 = 0.f, r1 = 0.f, i0v = 0.f, i1v = 0.f;
            if (q < DIM) {
                if (p < DIM)     { r0 = xre[base + p * DIM + q];
                                   i0v = xim[base + p * DIM + q]; }
                if (p + 1 < DIM) { r1 = xre[base + (p + 1) * DIM + q];
                                   i1v = xim[base + (p + 1) * DIM + q]; }
            }
            uint32_t h, l;
            hl_split(r0, r1, h, l);
            XrH[q * 12 + j] = h; XrL[q * 12 + j] = l;
            hl_split(i0v, i1v, h, l);
            XiH[q * 12 + j] = h; XiL[q * 12 + j] = l;
        }
        __syncthreads();

        // A fragments for this (warp, chunk): Ur/Ui hi+lo
        uint32_t WrHf[4], WrLf[4], WiHf[4], WiLf[4];
        {
            const int bA = ((warp * KT + c) * 32 + lane) * 4;
            const int mstr = 2 * 8 * KT * 32 * 4;   // mat stride
            const int sstr = 8 * KT * 32 * 4;       // split stride
            *(uint4*)WrHf = *(const uint4*)&g_A1[bA];
            *(uint4*)WrLf = *(const uint4*)&g_A1[bA + sstr];
            *(uint4*)WiHf = *(const uint4*)&g_A1[bA + mstr];
            *(uint4*)WiLf = *(const uint4*)&g_A1[bA + mstr + sstr];
        }

        #pragma unroll
        for (int n = 0; n < NT; ++n) {
            const int qb = (8 * n + nl) * 12;
            const uint32_t xrh0 = XrH[qb + mm],     xrh1 = XrH[qb + 4 + mm];
            const uint32_t xrl0 = XrL[qb + mm],     xrl1 = XrL[qb + 4 + mm];
            const uint32_t xih0 = XiH[qb + mm],     xih1 = XiH[qb + 4 + mm];
            const uint32_t xil0 = XiL[qb + mm],     xil1 = XiL[qb + 4 + mm];
            const uint32_t nih0 = xih0 ^ 0x80008000u, nih1 = xih1 ^ 0x80008000u;
            const uint32_t nil0 = xil0 ^ 0x80008000u, nil1 = xil1 ^ 0x80008000u;
            // P += Ur*Xr - Ui*Xi   (3-term splits)
            mma16816(P[n], WrHf, xrh0, xrh1);
            mma16816(P[n], WrHf, xrl0, xrl1);
            mma16816(P[n], WrLf, xrh0, xrh1);
            mma16816(P[n], WiHf, nih0, nih1);
            mma16816(P[n], WiHf, nil0, nil1);
            mma16816(P[n], WiLf, nih0, nih1);
            // Q += Ur*Xi + Ui*Xr
            mma16816(Q[n], WrHf, xih0, xih1);
            mma16816(Q[n], WrHf, xil0, xil1);
            mma16816(Q[n], WrLf, xih0, xih1);
            mma16816(Q[n], WiHf, xrh0, xrh1);
            mma16816(Q[n], WiHf, xrl0, xrl1);
            mma16816(Q[n], WiLf, xrh0, xrh1);
        }
    }

    // -------- stage 2: O = P Ur^T + Q Ui^T --------
    float O[NT][4];
    #pragma unroll
    for (int n = 0; n < NT; ++n)
        #pragma unroll
        for (int r = 0; r < 4; ++r) O[n][r] = 0.f;

    const int mstrB = 2 * KT * NT * 32 * 2;
    const int sstrB = KT * NT * 32 * 2;

    #pragma unroll
    for (int t = 0; t < KT; ++t) {
        // A frags from P/Q accumulators (register-local layout identity)
        uint32_t PAH[4], PAL[4], QAH[4], QAL[4];
        hl_split(P[2 * t][0], P[2 * t][1], PAH[0], PAL[0]);
        hl_split(P[2 * t][2], P[2 * t][3], PAH[1], PAL[1]);
        hl_split(Q[2 * t][0], Q[2 * t][1], QAH[0], QAL[0]);
        hl_split(Q[2 * t][2], Q[2 * t][3], QAH[1], QAL[1]);
        if (t < 6) {
            hl_split(P[2 * t + 1][0], P[2 * t + 1][1], PAH[2], PAL[2]);
            hl_split(P[2 * t + 1][2], P[2 * t + 1][3], PAH[3], PAL[3]);
            hl_split(Q[2 * t + 1][0], Q[2 * t + 1][1], QAH[2], QAL[2]);
            hl_split(Q[2 * t + 1][2], Q[2 * t + 1][3], QAH[3], QAL[3]);
        } else {
            PAH[2] = PAH[3] = PAL[2] = PAL[3] = 0u;
            QAH[2] = QAH[3] = QAL[2] = QAL[3] = 0u;
        }

        #pragma unroll
        for (int n = 0; n < NT; ++n) {
            const int bB = ((t * NT + n) * 32 + lane) * 2;
            uint2 brh = *(const uint2*)&g_B2[bB];                   // Ur hi
            uint2 brl = *(const uint2*)&g_B2[bB + sstrB];           // Ur lo
            uint2 bih = *(const uint2*)&g_B2[bB + mstrB];           // Ui hi
            uint2 bil = *(const uint2*)&g_B2[bB + mstrB + sstrB];   // Ui lo
            mma16816(O[n], PAH, brh.x, brh.y);
            mma16816(O[n], PAH, brl.x, brl.y);
            mma16816(O[n], PAL, brh.x, brh.y);
            mma16816(O[n], QAH, bih.x, bih.y);
            mma16816(O[n], QAH, bil.x, bil.y);
            mma16816(O[n], QAL, bih.x, bih.y);
        }
    }

    // -------- store (D layout: rows lane/4 & +8, cols 8n + 2*(lane%4)) ------
    const int r0 = warp * 16 + nl;
    #pragma unroll
    for (int n = 0; n < NT; ++n) {
        const int c0 = n * 8 + 2 * mm;
        if (c0 + 1 >= DIM) continue;
        if (r0 < DIM) {
            const int idx = base + r0 * DIM + c0;
            if (idx + 2 <= out_floats)
                *(float2*)&outf[idx] = make_float2(O[n][0], O[n][1]);
        }
        if (r0 + 8 < DIM) {
            const int idx = base + (r0 + 8) * DIM + c0;
            if (idx + 2 <= out_floats)
                *(float2*)&outf[idx] = make_float2(O[n][2], O[n][3]);
        }
    }
}

// Diagnostic fallback
__global__ void diag_mark_kernel(float* out) { out[0] = 0.0f; }

extern "C" void kernel_launch(void* const* d_in, const int* in_sizes, int n_in,
                              void* d_out, int out_size) {
    int smin = 0x7fffffff;
    for (int i = 0; i < n_in; ++i)
        if (in_sizes[i] < smin) smin = in_sizes[i];

    int unit = 0;
    if (smin == DIM)          unit = 1;
    else if (smin == DIM * 4) unit = 4;

    const float* xre = nullptr; const float* xim = nullptr;
    const float* theta = nullptr; const float* phi = nullptr;
    const float* diag = nullptr;
    int nbatch = 0, big = 0;
    bool ok = (unit != 0) && (n_in == 5);

    if (ok) {
        int norm[8];
        int diag_slot = -1;
        for (int i = 0; i < n_in; ++i) {
            norm[i] = in_sizes[i] / unit;
            if (norm[i] == DIM) diag_slot = i;
            if (norm[i] > big) big = norm[i];
        }
        if (diag_slot == 0 && norm[1] == KBS && norm[2] == KBS) {
            diag  = (const float*)d_in[0];
            phi   = (const float*)d_in[1];
            theta = (const float*)d_in[2];
            xre   = (const float*)d_in[3];
            xim   = (const float*)d_in[4];
        } else {
            for (int i = 0; i < n_in; ++i) {
                const float* p = (const float*)d_in[i];
                if (norm[i] == KBS)      { if (!theta) theta = p; else phi = p; }
                else if (norm[i] == DIM) { diag = p; }
                else if (norm[i] == big) { if (!xre) xre = p; else xim = p; }
            }
        }
        nbatch = big / NN;
        ok = xre && xim && theta && phi && diag &&
             nbatch > 0 && nbatch <= MAXB && (big == nbatch * NN);
    }

    if (!ok) {
        diag_mark_kernel<<<1, 1>>>((float*)d_out);
        return;
    }

    const int want = nbatch * NN;
    const int out_floats = (out_size < want) ? out_size : want;

    rot_prep<<<(KBS + 127) / 128, 128>>>(theta, phi, diag);
    build_U<<<DIM, 64>>>();
    frag_prep<<<128, 256>>>();
    fused_mma<<<nbatch, 256>>>(xre, xim, (float*)d_out, out_floats);
}